// round 2
// baseline (speedup 1.0000x reference)
#include <cuda_runtime.h>

#define NB 32
#define NL 2048
#define ND 768
#define NV 32000
#define SPLITS 16
#define LPS (NL / SPLITS)      // 128 tokens per split
#define ND4 (ND / 4)           // 192 float4 per token row

// Scratch (no device allocation allowed in kernel_launch)
__device__ float g_weights[NB * NL];              // normalized weights (1/norm folded in)
__device__ float g_partial[NB * SPLITS * ND];     // split partial sums

// -------- block reduce (1024 threads = 32 warps) --------
__device__ __forceinline__ float block_reduce_sum(float v, float* red) {
    __syncthreads();  // protect red[] reuse across consecutive calls
    int lane = threadIdx.x & 31;
    int wid  = threadIdx.x >> 5;
#pragma unroll
    for (int o = 16; o > 0; o >>= 1) v += __shfl_down_sync(0xffffffffu, v, o);
    if (lane == 0) red[wid] = v;
    __syncthreads();
    if (wid == 0) {
        v = (lane < (int)(blockDim.x >> 5)) ? red[lane] : 0.0f;
#pragma unroll
        for (int o = 16; o > 0; o >>= 1) v += __shfl_down_sync(0xffffffffu, v, o);
        if (lane == 0) red[0] = v;
    }
    __syncthreads();
    return red[0];
}

// -------- kernel 1: per-row histogram -> normalized weights --------
// one CTA per batch row; dynamic SMEM = NV u32 hist + 32 f32 reduce scratch
__global__ void __launch_bounds__(1024) weights_kernel(
    const int* __restrict__ mask,
    const int* __restrict__ ids,      // int32 (JAX x64-disabled downgrades int64)
    const float* __restrict__ idf,
    const float* __restrict__ alphap)
{
    extern __shared__ unsigned char smraw[];
    unsigned int* hist = (unsigned int*)smraw;
    float* red = (float*)(hist + NV);

    const int b   = blockIdx.x;
    const int tid = threadIdx.x;

    // zero histogram
    for (int i = tid; i < NV; i += 1024) hist[i] = 0u;
    __syncthreads();

    // each thread owns 2 tokens (2048 / 1024)
    const int l0 = b * NL + tid;
    const int l1 = l0 + 1024;
    const int m0 = mask[l0];
    const int m1 = mask[l1];
    int id0 = ids[l0];
    int id1 = ids[l1];
    // branch-free safety: clamp out-of-range ids (should never trigger)
    const int ok0 = ((unsigned)id0 < (unsigned)NV);
    const int ok1 = ((unsigned)id1 < (unsigned)NV);
    id0 = ok0 ? id0 : 0;
    id1 = ok1 ? id1 : 0;

    float nv_loc = 0.0f;
    if (m0 && ok0) { atomicAdd(&hist[id0], 1u); nv_loc += 1.0f; }
    if (m1 && ok1) { atomicAdd(&hist[id1], 1u); nv_loc += 1.0f; }
    __syncthreads();  // histogram complete

    const float n_valid = block_reduce_sum(nv_loc, red);
    const float inv_n   = 1.0f / fmaxf(n_valid, 1.0f);
    const float alpha   = *alphap;

    float w0 = 0.0f, w1 = 0.0f;
    if (m0 && ok0) w0 = 1.0f + alpha * ((float)hist[id0] * inv_n) * idf[id0];
    if (m1 && ok1) w1 = 1.0f + alpha * ((float)hist[id1] * inv_n) * idf[id1];

    const float wsum = block_reduce_sum(w0 + w1, red);
    const float inv_norm = 1.0f / fmaxf(wsum, 1e-12f);

    g_weights[l0] = w0 * inv_norm;
    g_weights[l1] = w1 * inv_norm;
}

// -------- kernel 2: streaming weighted sum over a token slab --------
// grid = (SPLITS, NB), 192 threads; each thread owns one float4 column chunk
__global__ void __launch_bounds__(192) pool_kernel(const float* __restrict__ hid)
{
    const int s = blockIdx.x;
    const int b = blockIdx.y;
    const int tid = threadIdx.x;

    __shared__ float w[LPS];
    if (tid < LPS) w[tid] = g_weights[b * NL + s * LPS + tid];
    __syncthreads();

    const float4* base = (const float4*)hid + ((size_t)b * NL + (size_t)s * LPS) * ND4;

    float4 acc = make_float4(0.f, 0.f, 0.f, 0.f);
#pragma unroll 4
    for (int l = 0; l < LPS; l++) {
        float4 v = base[(size_t)l * ND4 + tid];
        float wl = w[l];
        acc.x += v.x * wl;
        acc.y += v.y * wl;
        acc.z += v.z * wl;
        acc.w += v.w * wl;
    }

    float4* out = (float4*)(g_partial + ((size_t)b * SPLITS + s) * ND);
    out[tid] = acc;
}

// -------- kernel 3: reduce split partials --------
__global__ void __launch_bounds__(256) reduce_kernel(float* __restrict__ out)
{
    const int i = blockIdx.x * blockDim.x + threadIdx.x;  // over B*D
    if (i >= NB * ND) return;
    const int b = i / ND;
    const int d = i - b * ND;
    float s = 0.0f;
#pragma unroll
    for (int sp = 0; sp < SPLITS; sp++)
        s += g_partial[((size_t)b * SPLITS + sp) * ND + d];
    out[i] = s;
}

extern "C" void kernel_launch(void* const* d_in, const int* in_sizes, int n_in,
                              void* d_out, int out_size)
{
    const float* hid   = (const float*)d_in[0];
    const int*   mask  = (const int*)d_in[1];
    const int*   ids   = (const int*)d_in[2];
    const float* idf   = (const float*)d_in[3];
    const float* alpha = (const float*)d_in[4];
    float*       out   = (float*)d_out;

    const int smem = NV * sizeof(unsigned int) + 32 * sizeof(float);
    cudaFuncSetAttribute(weights_kernel,
                         cudaFuncAttributeMaxDynamicSharedMemorySize, smem);

    weights_kernel<<<NB, 1024, smem>>>(mask, ids, idf, alpha);

    dim3 g2(SPLITS, NB);
    pool_kernel<<<g2, 192>>>(hid);

    reduce_kernel<<<(NB * ND + 255) / 256, 256>>>(out);
}

// round 4
// speedup vs baseline: 1.0248x; 1.0248x over previous
#include <cuda_runtime.h>

#define NB 32
#define NL 2048
#define ND 768
#define NV 32000
#define SPLITS 16
#define LPS (NL / SPLITS)      // 128 tokens per split
#define ND4 (ND / 4)           // 192 float4 per token row

// Scratch (no device allocation allowed in kernel_launch)
__device__ float g_weights[NB * NL];   // normalized weights (1/norm folded in)

// -------- block reduce (1024 threads = 32 warps) --------
__device__ __forceinline__ float block_reduce_sum(float v, float* red) {
    __syncthreads();  // protect red[] reuse across consecutive calls
    int lane = threadIdx.x & 31;
    int wid  = threadIdx.x >> 5;
#pragma unroll
    for (int o = 16; o > 0; o >>= 1) v += __shfl_down_sync(0xffffffffu, v, o);
    if (lane == 0) red[wid] = v;
    __syncthreads();
    if (wid == 0) {
        v = (lane < (int)(blockDim.x >> 5)) ? red[lane] : 0.0f;
#pragma unroll
        for (int o = 16; o > 0; o >>= 1) v += __shfl_down_sync(0xffffffffu, v, o);
        if (lane == 0) red[0] = v;
    }
    __syncthreads();
    return red[0];
}

// -------- kernel 1: per-row histogram -> normalized weights, zero d_out --------
// one CTA per batch row; dynamic SMEM = NV u32 hist + 32 f32 reduce scratch
__global__ void __launch_bounds__(1024) weights_kernel(
    const int* __restrict__ mask,
    const int* __restrict__ ids,      // int32 (JAX x64-disabled downgrades int64)
    const float* __restrict__ idf,
    const float* __restrict__ alphap,
    float* __restrict__ out)
{
    extern __shared__ unsigned char smraw[];
    unsigned int* hist = (unsigned int*)smraw;
    float* red = (float*)(hist + NV);

    const int b   = blockIdx.x;
    const int tid = threadIdx.x;

    // zero d_out row for this batch (pool kernel accumulates atomically)
    if (tid < ND) out[b * ND + tid] = 0.0f;

    // zero histogram with 16B stores: 32000 u32 = 8000 uint4
    {
        uint4 z = make_uint4(0u, 0u, 0u, 0u);
        uint4* h4 = (uint4*)hist;
#pragma unroll
        for (int i = 0; i < NV / 4 / 1024 + 1; i++) {
            int idx = tid + i * 1024;
            if (idx < NV / 4) h4[idx] = z;
        }
    }
    __syncthreads();

    // each thread owns 2 tokens (2048 / 1024)
    const int l0 = b * NL + tid;
    const int l1 = l0 + 1024;
    const int m0 = mask[l0];
    const int m1 = mask[l1];
    int id0 = ids[l0];
    int id1 = ids[l1];
    const int ok0 = ((unsigned)id0 < (unsigned)NV);
    const int ok1 = ((unsigned)id1 < (unsigned)NV);
    id0 = ok0 ? id0 : 0;
    id1 = ok1 ? id1 : 0;

    float nv_loc = 0.0f;
    if (m0 && ok0) { atomicAdd(&hist[id0], 1u); nv_loc += 1.0f; }
    if (m1 && ok1) { atomicAdd(&hist[id1], 1u); nv_loc += 1.0f; }
    __syncthreads();  // histogram complete

    const float n_valid = block_reduce_sum(nv_loc, red);
    const float inv_n   = 1.0f / fmaxf(n_valid, 1.0f);
    const float alpha   = *alphap;

    float w0 = 0.0f, w1 = 0.0f;
    if (m0 && ok0) w0 = 1.0f + alpha * ((float)hist[id0] * inv_n) * idf[id0];
    if (m1 && ok1) w1 = 1.0f + alpha * ((float)hist[id1] * inv_n) * idf[id1];

    const float wsum = block_reduce_sum(w0 + w1, red);
    const float inv_norm = 1.0f / fmaxf(wsum, 1e-12f);

    g_weights[l0] = w0 * inv_norm;
    g_weights[l1] = w1 * inv_norm;
}

// -------- kernel 2: streaming weighted sum, atomic accumulate into d_out --------
// grid = (SPLITS, NB), 192 threads; each thread owns one float4 column chunk
__global__ void __launch_bounds__(192) pool_kernel(
    const float* __restrict__ hid,
    float* __restrict__ out)
{
    const int s = blockIdx.x;
    const int b = blockIdx.y;
    const int tid = threadIdx.x;

    __shared__ float w[LPS];
    if (tid < LPS) w[tid] = g_weights[b * NL + s * LPS + tid];
    __syncthreads();

    const float4* base = (const float4*)hid + ((size_t)b * NL + (size_t)s * LPS) * ND4;

    float4 acc = make_float4(0.f, 0.f, 0.f, 0.f);
#pragma unroll 8
    for (int l = 0; l < LPS; l++) {
        float4 v = base[(size_t)l * ND4 + tid];
        float wl = w[l];
        acc.x += v.x * wl;
        acc.y += v.y * wl;
        acc.z += v.z * wl;
        acc.w += v.w * wl;
    }

    float* o = out + (size_t)b * ND + tid * 4;
    atomicAdd(o + 0, acc.x);
    atomicAdd(o + 1, acc.y);
    atomicAdd(o + 2, acc.z);
    atomicAdd(o + 3, acc.w);
}

extern "C" void kernel_launch(void* const* d_in, const int* in_sizes, int n_in,
                              void* d_out, int out_size)
{
    const float* hid   = (const float*)d_in[0];
    const int*   mask  = (const int*)d_in[1];
    const int*   ids   = (const int*)d_in[2];
    const float* idf   = (const float*)d_in[3];
    const float* alpha = (const float*)d_in[4];
    float*       out   = (float*)d_out;

    const int smem = NV * sizeof(unsigned int) + 32 * sizeof(float);
    cudaFuncSetAttribute(weights_kernel,
                         cudaFuncAttributeMaxDynamicSharedMemorySize, smem);

    weights_kernel<<<NB, 1024, smem>>>(mask, ids, idf, alpha, out);

    dim3 g2(SPLITS, NB);
    pool_kernel<<<g2, 192>>>(hid, out);
}

// round 5
// speedup vs baseline: 1.0751x; 1.0490x over previous
#include <cuda_runtime.h>

#define NB 32
#define NL 2048
#define ND 768
#define NV 32000
#define SPLITS 32
#define LPS (NL / SPLITS)      // 64 tokens per split
#define ND4 (ND / 4)           // 192 float4 per token row

// Scratch (no device allocation allowed in kernel_launch)
__device__ float g_weights[NB * NL];   // normalized weights (1/norm folded in)

// -------- block reduce (1024 threads = 32 warps) --------
__device__ __forceinline__ float block_reduce_sum(float v, float* red) {
    __syncthreads();  // protect red[] reuse across consecutive calls
    int lane = threadIdx.x & 31;
    int wid  = threadIdx.x >> 5;
#pragma unroll
    for (int o = 16; o > 0; o >>= 1) v += __shfl_down_sync(0xffffffffu, v, o);
    if (lane == 0) red[wid] = v;
    __syncthreads();
    if (wid == 0) {
        v = (lane < (int)(blockDim.x >> 5)) ? red[lane] : 0.0f;
#pragma unroll
        for (int o = 16; o > 0; o >>= 1) v += __shfl_down_sync(0xffffffffu, v, o);
        if (lane == 0) red[0] = v;
    }
    __syncthreads();
    return red[0];
}

// -------- kernel 1: per-row histogram -> normalized weights, zero d_out --------
// one CTA per batch row; dynamic SMEM = NV u32 hist + 32 f32 reduce scratch
__global__ void __launch_bounds__(1024) weights_kernel(
    const int* __restrict__ mask,
    const int* __restrict__ ids,      // int32 (JAX x64-disabled downgrades int64)
    const float* __restrict__ idf,
    const float* __restrict__ alphap,
    float* __restrict__ out)
{
    extern __shared__ unsigned char smraw[];
    unsigned int* hist = (unsigned int*)smraw;
    float* red = (float*)(hist + NV);

    const int b   = blockIdx.x;
    const int tid = threadIdx.x;

    // zero d_out row for this batch (pool kernel accumulates atomically)
    if (tid < ND) out[b * ND + tid] = 0.0f;

    // zero histogram with 16B stores: 32000 u32 = 8000 uint4
    {
        uint4 z = make_uint4(0u, 0u, 0u, 0u);
        uint4* h4 = (uint4*)hist;
#pragma unroll
        for (int i = 0; i < NV / 4 / 1024 + 1; i++) {
            int idx = tid + i * 1024;
            if (idx < NV / 4) h4[idx] = z;
        }
    }
    __syncthreads();

    // each thread owns 2 tokens (2048 / 1024)
    const int l0 = b * NL + tid;
    const int l1 = l0 + 1024;
    const int m0 = mask[l0];
    const int m1 = mask[l1];
    int id0 = ids[l0];
    int id1 = ids[l1];
    const int ok0 = ((unsigned)id0 < (unsigned)NV);
    const int ok1 = ((unsigned)id1 < (unsigned)NV);
    id0 = ok0 ? id0 : 0;
    id1 = ok1 ? id1 : 0;

    float nv_loc = 0.0f;
    if (m0 && ok0) { atomicAdd(&hist[id0], 1u); nv_loc += 1.0f; }
    if (m1 && ok1) { atomicAdd(&hist[id1], 1u); nv_loc += 1.0f; }
    __syncthreads();  // histogram complete

    const float n_valid = block_reduce_sum(nv_loc, red);
    const float inv_n   = 1.0f / fmaxf(n_valid, 1.0f);
    const float alpha   = *alphap;

    float w0 = 0.0f, w1 = 0.0f;
    if (m0 && ok0) w0 = 1.0f + alpha * ((float)hist[id0] * inv_n) * idf[id0];
    if (m1 && ok1) w1 = 1.0f + alpha * ((float)hist[id1] * inv_n) * idf[id1];

    const float wsum = block_reduce_sum(w0 + w1, red);
    const float inv_norm = 1.0f / fmaxf(wsum, 1e-12f);

    g_weights[l0] = w0 * inv_norm;
    g_weights[l1] = w1 * inv_norm;
}

// -------- kernel 2: streaming weighted sum, atomic accumulate into d_out --------
// grid = (SPLITS, NB), 192 threads; each thread owns one float4 column chunk
__global__ void __launch_bounds__(192) pool_kernel(
    const float* __restrict__ hid,
    float* __restrict__ out)
{
    const int s = blockIdx.x;
    const int b = blockIdx.y;
    const int tid = threadIdx.x;

    __shared__ float w[LPS];
    if (tid < LPS) w[tid] = g_weights[b * NL + s * LPS + tid];
    __syncthreads();

    const float4* base = (const float4*)hid + ((size_t)b * NL + (size_t)s * LPS) * ND4;

    float4 acc = make_float4(0.f, 0.f, 0.f, 0.f);
#pragma unroll 8
    for (int l = 0; l < LPS; l++) {
        float4 v = base[(size_t)l * ND4 + tid];
        float wl = w[l];
        acc.x += v.x * wl;
        acc.y += v.y * wl;
        acc.z += v.z * wl;
        acc.w += v.w * wl;
    }

    float* o = out + (size_t)b * ND + tid * 4;
    atomicAdd(o + 0, acc.x);
    atomicAdd(o + 1, acc.y);
    atomicAdd(o + 2, acc.z);
    atomicAdd(o + 3, acc.w);
}

extern "C" void kernel_launch(void* const* d_in, const int* in_sizes, int n_in,
                              void* d_out, int out_size)
{
    const float* hid   = (const float*)d_in[0];
    const int*   mask  = (const int*)d_in[1];
    const int*   ids   = (const int*)d_in[2];
    const float* idf   = (const float*)d_in[3];
    const float* alpha = (const float*)d_in[4];
    float*       out   = (float*)d_out;

    const int smem = NV * sizeof(unsigned int) + 32 * sizeof(float);
    cudaFuncSetAttribute(weights_kernel,
                         cudaFuncAttributeMaxDynamicSharedMemorySize, smem);

    weights_kernel<<<NB, 1024, smem>>>(mask, ids, idf, alpha, out);

    dim3 g2(SPLITS, NB);
    pool_kernel<<<g2, 192>>>(hid, out);
}